// round 2
// baseline (speedup 1.0000x reference)
#include <cuda_runtime.h>
#include <stdint.h>

// N = 256^3 voxels. d_out layout: [out (N floats)][onehot ch0 (N)][ch1 (N)][ch2 (N)]
#define NVOX (256u * 256u * 256u)
#define NV4  (NVOX / 4u)          // 4,194,304 vec4 items

__device__ __forceinline__ void stg_cs_v4(float* p, float4 v) {
    asm volatile("st.global.cs.v4.f32 [%0], {%1,%2,%3,%4};"
                 :: "l"(p), "f"(v.x), "f"(v.y), "f"(v.z), "f"(v.w) : "memory");
}

__device__ __forceinline__ void process4(const int4 lab, const float4 p,
                                         const float2* __restrict__ lut,
                                         float4& o, float4& h0, float4& h1, float4& h2) {
    float2 ex = lut[lab.x & 255];
    float2 ey = lut[lab.y & 255];
    float2 ez = lut[lab.z & 255];
    float2 ew = lut[lab.w & 255];
    o.x = p.x * ex.x;  o.y = p.y * ey.x;  o.z = p.z * ez.x;  o.w = p.w * ew.x;
    h0.x = (ex.y == 0.0f) ? 1.0f : 0.0f;
    h0.y = (ey.y == 0.0f) ? 1.0f : 0.0f;
    h0.z = (ez.y == 0.0f) ? 1.0f : 0.0f;
    h0.w = (ew.y == 0.0f) ? 1.0f : 0.0f;
    h1.x = (ex.y == 1.0f) ? 1.0f : 0.0f;
    h1.y = (ey.y == 1.0f) ? 1.0f : 0.0f;
    h1.z = (ez.y == 1.0f) ? 1.0f : 0.0f;
    h1.w = (ew.y == 1.0f) ? 1.0f : 0.0f;
    h2.x = (ex.y == 2.0f) ? 1.0f : 0.0f;
    h2.y = (ey.y == 2.0f) ? 1.0f : 0.0f;
    h2.z = (ez.y == 2.0f) ? 1.0f : 0.0f;
    h2.w = (ew.y == 2.0f) ? 1.0f : 0.0f;
}

__global__ __launch_bounds__(256, 8)
void yibei_synth_kernel(const int*   __restrict__ labels,
                        const float* __restrict__ id_intensity,
                        const int*   __restrict__ id_is_dark,
                        const float* __restrict__ par,
                        float*       __restrict__ out)
{
    // Combined LUT: .x = scaling (id 0 -> 1.0), .y = class (0=bg, 1=dark, 2=bright)
    __shared__ float2 lut[256];
    const int t = threadIdx.x;   // blockDim.x == 256
    {
        float s = (t == 0) ? 1.0f : __ldg(id_intensity + t);
        float c = (t == 0) ? 0.0f : ((__ldg(id_is_dark + t) == 1) ? 1.0f : 2.0f);
        lut[t] = make_float2(s, c);
    }
    __syncthreads();

    // Each block covers 512 consecutive vec4s; each thread does 2 (t and t+256).
    const unsigned ia = blockIdx.x * 512u + t;
    const unsigned ib = ia + 256u;

    // Front-batch all global loads for maximum MLP.
    const int4   labA = __ldg(((const int4*)labels) + ia);
    const int4   labB = __ldg(((const int4*)labels) + ib);
    const float4 pA   = __ldg(((const float4*)par)  + ia);
    const float4 pB   = __ldg(((const float4*)par)  + ib);

    float4 oA, h0A, h1A, h2A;
    float4 oB, h0B, h1B, h2B;
    process4(labA, pA, lut, oA, h0A, h1A, h2A);
    process4(labB, pB, lut, oB, h0B, h1B, h2B);

    float4* ovec = (float4*)out;
    stg_cs_v4((float*)(ovec + ia),            oA);
    stg_cs_v4((float*)(ovec + ib),            oB);
    stg_cs_v4((float*)(ovec + (NV4 + ia)),      h0A);
    stg_cs_v4((float*)(ovec + (NV4 + ib)),      h0B);
    stg_cs_v4((float*)(ovec + (2u * NV4 + ia)), h1A);
    stg_cs_v4((float*)(ovec + (2u * NV4 + ib)), h1B);
    stg_cs_v4((float*)(ovec + (3u * NV4 + ia)), h2A);
    stg_cs_v4((float*)(ovec + (3u * NV4 + ib)), h2B);
}

extern "C" void kernel_launch(void* const* d_in, const int* in_sizes, int n_in,
                              void* d_out, int out_size)
{
    const int*   labels       = (const int*)  d_in[0];
    const float* id_intensity = (const float*)d_in[1];
    const int*   id_is_dark   = (const int*)  d_in[2];
    const float* parenchyma   = (const float*)d_in[3];
    float*       out          = (float*)d_out;

    const unsigned grid = NV4 / 512u;          // 8192 blocks
    yibei_synth_kernel<<<grid, 256>>>(labels, id_intensity, id_is_dark, parenchyma, out);
}

// round 4
// speedup vs baseline: 1.0149x; 1.0149x over previous
#include <cuda_runtime.h>
#include <stdint.h>

// N = 256^3 voxels. d_out layout: [out (N floats)][onehot ch0 (N)][ch1 (N)][ch2 (N)]
#define NVOX (256u * 256u * 256u)
#define NV4  (NVOX / 4u)          // 4,194,304 vec4 items

__device__ __forceinline__ void stg_cs_v4(float* p, float4 v) {
    asm volatile("st.global.cs.v4.f32 [%0], {%1,%2,%3,%4};"
                 :: "l"(p), "f"(v.x), "f"(v.y), "f"(v.z), "f"(v.w) : "memory");
}

__global__ __launch_bounds__(256, 8)
void yibei_synth_kernel(const int*   __restrict__ labels,
                        const float* __restrict__ id_intensity,
                        const int*   __restrict__ id_is_dark,
                        const float* __restrict__ par,
                        float*       __restrict__ out)
{
    // Combined LUT: .x = scaling (id 0 -> 1.0), .y = class (0=bg, 1=dark, 2=bright) as float
    __shared__ float2 lut[256];
    const int t = threadIdx.x;   // blockDim.x == 256
    {
        float s = (t == 0) ? 1.0f : __ldg(id_intensity + t);
        float c = (t == 0) ? 0.0f : ((__ldg(id_is_dark + t) == 1) ? 1.0f : 2.0f);
        lut[t] = make_float2(s, c);
    }
    __syncthreads();

    const unsigned i4 = blockIdx.x * 256u + t;   // vec4 index, grid sized exactly

    const int4   lab = __ldg(((const int4*)labels) + i4);
    const float4 p   = __ldg(((const float4*)par)  + i4);

    const float2 ex = lut[lab.x & 255];
    const float2 ey = lut[lab.y & 255];
    const float2 ez = lut[lab.z & 255];
    const float2 ew = lut[lab.w & 255];

    float4 o, h0, h1, h2;
    o.x = p.x * ex.x;  o.y = p.y * ey.x;  o.z = p.z * ez.x;  o.w = p.w * ew.x;

    h0.x = (ex.y == 0.0f) ? 1.0f : 0.0f;
    h0.y = (ey.y == 0.0f) ? 1.0f : 0.0f;
    h0.z = (ez.y == 0.0f) ? 1.0f : 0.0f;
    h0.w = (ew.y == 0.0f) ? 1.0f : 0.0f;

    h1.x = (ex.y == 1.0f) ? 1.0f : 0.0f;
    h1.y = (ey.y == 1.0f) ? 1.0f : 0.0f;
    h1.z = (ez.y == 1.0f) ? 1.0f : 0.0f;
    h1.w = (ew.y == 1.0f) ? 1.0f : 0.0f;

    h2.x = (ex.y == 2.0f) ? 1.0f : 0.0f;
    h2.y = (ey.y == 2.0f) ? 1.0f : 0.0f;
    h2.z = (ez.y == 2.0f) ? 1.0f : 0.0f;
    h2.w = (ew.y == 2.0f) ? 1.0f : 0.0f;

    float4* ovec = (float4*)out;
    stg_cs_v4((float*)(ovec + i4),             o);
    stg_cs_v4((float*)(ovec + (NV4 + i4)),       h0);
    stg_cs_v4((float*)(ovec + (2u * NV4 + i4)),  h1);
    stg_cs_v4((float*)(ovec + (3u * NV4 + i4)),  h2);
}

extern "C" void kernel_launch(void* const* d_in, const int* in_sizes, int n_in,
                              void* d_out, int out_size)
{
    const int*   labels       = (const int*)  d_in[0];
    const float* id_intensity = (const float*)d_in[1];
    const int*   id_is_dark   = (const int*)  d_in[2];
    const float* parenchyma   = (const float*)d_in[3];
    float*       out          = (float*)d_out;

    const unsigned grid = NV4 / 256u;          // 16,384 blocks
    yibei_synth_kernel<<<grid, 256>>>(labels, id_intensity, id_is_dark, parenchyma, out);
}